// round 4
// baseline (speedup 1.0000x reference)
#include <cuda_runtime.h>
#include <cstdint>

#define M_TOK 8192
#define K_DIM 4096
#define N_OUT 4096
#define NGRP  16

// ---- scratch (device globals; no allocation allowed) ----
__device__ __align__(16) int8_t g_q[(size_t)M_TOK * K_DIM];     // quantized activations
__device__ float g_sx[M_TOK];                                    // per-token scale
__device__ float g_zp[M_TOK];                                    // per-token zero point
__device__ __align__(16) int8_t g_wz[(size_t)N_OUT * K_DIM];    // w - zeros (int8)
__device__ float g_wsum[N_OUT];                                  // sum_g s[o,g]*colsum_g

// ============================================================================
// Kernel 1: per-token asymmetric int8 quantization (matches torchao math)
// ============================================================================
__global__ __launch_bounds__(256) void quant_kernel(const float* __restrict__ x) {
    int row = blockIdx.x;
    int tid = threadIdx.x;
    const float4* xr4 = reinterpret_cast<const float4*>(x + (size_t)row * K_DIM) + tid * 4;

    float4 v[4];
#pragma unroll
    for (int i = 0; i < 4; i++) v[i] = xr4[i];

    float mn = 0.0f, mx = 0.0f;
#pragma unroll
    for (int i = 0; i < 4; i++) {
        mn = fminf(mn, fminf(fminf(v[i].x, v[i].y), fminf(v[i].z, v[i].w)));
        mx = fmaxf(mx, fmaxf(fmaxf(v[i].x, v[i].y), fmaxf(v[i].z, v[i].w)));
    }
#pragma unroll
    for (int off = 16; off; off >>= 1) {
        mn = fminf(mn, __shfl_xor_sync(0xffffffffu, mn, off));
        mx = fmaxf(mx, __shfl_xor_sync(0xffffffffu, mx, off));
    }
    __shared__ float smn[8], smx[8];
    if ((tid & 31) == 0) { smn[tid >> 5] = mn; smx[tid >> 5] = mx; }
    __syncthreads();
    mn = smn[0]; mx = smx[0];
#pragma unroll
    for (int i = 1; i < 8; i++) { mn = fminf(mn, smn[i]); mx = fmaxf(mx, smx[i]); }

    float scale = fmaxf((mx - mn) / 255.0f, 1.1920928955078125e-07f);
    float a = mn / scale, b = mx / scale;
    float t = (-128.0f + a) + (127.0f + b);
    float zp0 = (t > 0.0f) ? (-128.0f - a) : (127.0f - b);
    float zpf = fminf(fmaxf(rintf(zp0), -128.0f), 127.0f);

    const float* pv = reinterpret_cast<const float*>(v);
    uint32_t packed[4];
#pragma unroll
    for (int w = 0; w < 4; w++) {
        uint32_t p = 0;
#pragma unroll
        for (int j = 0; j < 4; j++) {
            float qf = rintf(pv[w * 4 + j] / scale) + zpf;
            qf = fminf(fmaxf(qf, -128.0f), 127.0f);
            int qi = (int)qf;
            p |= (uint32_t)(uint8_t)(int8_t)qi << (8 * j);
        }
        packed[w] = p;
    }
    reinterpret_cast<uint4*>(g_q + (size_t)row * K_DIM)[tid] =
        make_uint4(packed[0], packed[1], packed[2], packed[3]);
    if (tid == 0) { g_sx[row] = scale; g_zp[row] = zpf; }
}

// ============================================================================
// Kernel 2: weight prep — W arrives as int32 (harness upcast of int8)
// ============================================================================
__global__ __launch_bounds__(256) void wprep_kernel(const int* __restrict__ W,
                                                    const float* __restrict__ scales,
                                                    const float* __restrict__ zeros) {
    int o = blockIdx.x;
    int tid = threadIdx.x;
    int g = tid >> 4;
    int zi = __float2int_rn(zeros[o * NGRP + g]);

    const int4* Wrow = reinterpret_cast<const int4*>(W + (size_t)o * K_DIM) + tid * 4;
    uint32_t ow[4];
    int s = 0;
#pragma unroll
    for (int c = 0; c < 4; c++) {
        int4 w4 = Wrow[c];
        int v0 = w4.x - zi, v1 = w4.y - zi, v2 = w4.z - zi, v3 = w4.w - zi;
        s += v0 + v1 + v2 + v3;
        ow[c] = ((uint32_t)(uint8_t)(int8_t)v0)
              | ((uint32_t)(uint8_t)(int8_t)v1 << 8)
              | ((uint32_t)(uint8_t)(int8_t)v2 << 16)
              | ((uint32_t)(uint8_t)(int8_t)v3 << 24);
    }
    reinterpret_cast<uint4*>(g_wz + (size_t)o * K_DIM)[tid] =
        make_uint4(ow[0], ow[1], ow[2], ow[3]);

    __shared__ int ssum[256];
    __shared__ float gs[NGRP];
    ssum[tid] = s;
    __syncthreads();
    if (tid < NGRP) {
        int cs = 0;
#pragma unroll
        for (int j = 0; j < 16; j++) cs += ssum[tid * 16 + j];
        gs[tid] = scales[o * NGRP + tid] * (float)cs;
    }
    __syncthreads();
    if (tid == 0) {
        float acc = 0.0f;
#pragma unroll
        for (int j = 0; j < NGRP; j++) acc += gs[j];
        g_wsum[o] = acc;
    }
}

// ============================================================================
// Kernel 3: pipelined int8 IMMA GEMM (cp.async 4-stage, ldmatrix, group fold)
// ============================================================================
#define BM 128
#define BN 128
#define BK 64
#define NSTAGE 4
#define TILE_B (BM * BK)                 // 8192 bytes (A or B tile)
#define STAGE_B (2 * TILE_B)             // 16384
#define SS_OFF (NSTAGE * STAGE_B)        // scales region offset
#define SMEM_DYN (SS_OFF + NGRP * BN * 4 + 1024)
#define KITERS (K_DIM / BK)              // 64

__device__ __forceinline__ uint32_t s2u(const void* p) {
    uint32_t a;
    asm("{ .reg .u64 t; cvta.to.shared.u64 t, %1; cvt.u32.u64 %0, t; }" : "=r"(a) : "l"(p));
    return a;
}
// tile-local swizzled offset: rows (64B) packed 2-per-128B line, SW128 xor
__device__ __forceinline__ uint32_t swz(uint32_t r, uint32_t c16) {
    uint32_t off = (r >> 1) * 128 + (r & 1) * 64 + c16 * 16;
    return off ^ ((off >> 3) & 0x70);
}
__device__ __forceinline__ void ldsm4(uint32_t& d0, uint32_t& d1, uint32_t& d2, uint32_t& d3,
                                      uint32_t addr) {
    asm volatile("ldmatrix.sync.aligned.m8n8.x4.shared.b16 {%0,%1,%2,%3}, [%4];"
                 : "=r"(d0), "=r"(d1), "=r"(d2), "=r"(d3) : "r"(addr));
}
__device__ __forceinline__ void mma_s8(int& c0, int& c1, int& c2, int& c3,
                                       uint32_t a0, uint32_t a1, uint32_t a2, uint32_t a3,
                                       uint32_t b0, uint32_t b1) {
    asm volatile(
        "mma.sync.aligned.m16n8k32.row.col.s32.s8.s8.s32 "
        "{%0,%1,%2,%3}, {%4,%5,%6,%7}, {%8,%9}, {%0,%1,%2,%3};\n"
        : "+r"(c0), "+r"(c1), "+r"(c2), "+r"(c3)
        : "r"(a0), "r"(a1), "r"(a2), "r"(a3), "r"(b0), "r"(b1));
}

__global__ __launch_bounds__(256, 1) void gemm_kernel(const float* __restrict__ scales,
                                                      float* __restrict__ out) {
    extern __shared__ char smem_raw[];
    char* sm = (char*)(((uintptr_t)smem_raw + 1023) & ~(uintptr_t)1023);
    uint32_t sbase = s2u(sm);
    float* Ss = reinterpret_cast<float*>(sm + SS_OFF);

    int tid = threadIdx.x, lane = tid & 31, wid = tid >> 5;
    int warpm = wid & 1, warpn = wid >> 1;        // 2 x 4 warp grid, warp tile 64x32
    int gid = lane >> 2, tig = lane & 3;
    int bn = blockIdx.x, bm = blockIdx.y;

    // stage scales [g][col]
    for (int i = tid; i < NGRP * BN; i += 256) {
        int g = i >> 7, col = i & 127;
        Ss[i] = scales[(size_t)(bn * BN + col) * NGRP + g];
    }

    // per-lane ldmatrix swizzled offsets (tile-local)
    uint32_t aoff[4][2], boff[2][2];
    {
        int g8 = lane >> 3, rin = lane & 7;
#pragma unroll
        for (int mt = 0; mt < 4; mt++)
#pragma unroll
            for (int ks = 0; ks < 2; ks++)
                aoff[mt][ks] = swz(warpm * 64 + mt * 16 + (g8 & 1) * 8 + rin, ks * 2 + (g8 >> 1));
#pragma unroll
        for (int p = 0; p < 2; p++)
#pragma unroll
            for (int ks = 0; ks < 2; ks++)
                boff[p][ks] = swz(warpn * 32 + p * 16 + (g8 >> 1) * 8 + rin, ks * 2 + (g8 & 1));
    }

    const int8_t* Ag = g_q + (size_t)bm * BM * K_DIM;
    const int8_t* Bg = g_wz + (size_t)bn * BN * K_DIM;

    // per-thread cp.async assignments
    uint32_t sa_off[2], sb_off[2];
    const int8_t* ga_ptr[2];
    const int8_t* gb_ptr[2];
#pragma unroll
    for (int i = 0; i < 2; i++) {
        int seg = tid + i * 256;
        int r = seg >> 2, c = seg & 3;
        sa_off[i] = swz(r, c);
        sb_off[i] = TILE_B + sa_off[i];
        ga_ptr[i] = Ag + (size_t)r * K_DIM + c * 16;
        gb_ptr[i] = Bg + (size_t)r * K_DIM + c * 16;
    }

#define ISSUE(kc)                                                                     \
    {                                                                                 \
        uint32_t st = sbase + ((kc) & 3) * STAGE_B;                                   \
        _Pragma("unroll") for (int i = 0; i < 2; i++) {                               \
            asm volatile("cp.async.cg.shared.global [%0], [%1], 16;"                  \
                         :: "r"(st + sa_off[i]), "l"(ga_ptr[i] + (kc) * BK) : "memory"); \
            asm volatile("cp.async.cg.shared.global [%0], [%1], 16;"                  \
                         :: "r"(st + sb_off[i]), "l"(gb_ptr[i] + (kc) * BK) : "memory"); \
        }                                                                             \
    }

    int c[4][4][4];
    float f[4][4][4];
#pragma unroll
    for (int mt = 0; mt < 4; mt++)
#pragma unroll
        for (int nt = 0; nt < 4; nt++)
#pragma unroll
            for (int r = 0; r < 4; r++) { c[mt][nt][r] = 0; f[mt][nt][r] = 0.0f; }

    // prologue: fill 3 stages
#pragma unroll
    for (int s = 0; s < NSTAGE - 1; s++) {
        ISSUE(s);
        asm volatile("cp.async.commit_group;" ::: "memory");
    }

    for (int kc = 0; kc < KITERS; ++kc) {
        asm volatile("cp.async.wait_group 2;" ::: "memory");
        __syncthreads();

        if (kc + NSTAGE - 1 < KITERS) ISSUE(kc + NSTAGE - 1);
        asm volatile("cp.async.commit_group;" ::: "memory");

        uint32_t sA = sbase + (kc & 3) * STAGE_B;
        uint32_t sB = sA + TILE_B;
#pragma unroll
        for (int ks = 0; ks < 2; ks++) {
            uint32_t a[4][4], b[2][4];
#pragma unroll
            for (int mt = 0; mt < 4; mt++)
                ldsm4(a[mt][0], a[mt][1], a[mt][2], a[mt][3], sA + aoff[mt][ks]);
#pragma unroll
            for (int p = 0; p < 2; p++)
                ldsm4(b[p][0], b[p][1], b[p][2], b[p][3], sB + boff[p][ks]);
#pragma unroll
            for (int mt = 0; mt < 4; mt++)
#pragma unroll
                for (int nt = 0; nt < 4; nt++)
                    mma_s8(c[mt][nt][0], c[mt][nt][1], c[mt][nt][2], c[mt][nt][3],
                           a[mt][0], a[mt][1], a[mt][2], a[mt][3],
                           b[nt >> 1][(nt & 1) * 2], b[nt >> 1][(nt & 1) * 2 + 1]);
        }

        // group boundary every 4 chunks (256 K): exact fold into fp32
        if ((kc & 3) == 3) {
            int g = kc >> 2;
#pragma unroll
            for (int nt = 0; nt < 4; ++nt) {
                int col = warpn * 32 + nt * 8 + tig * 2;
                float s0 = Ss[g * BN + col];
                float s1 = Ss[g * BN + col + 1];
#pragma unroll
                for (int mt = 0; mt < 4; ++mt) {
                    f[mt][nt][0] = fmaf((float)c[mt][nt][0], s0, f[mt][nt][0]);
                    f[mt][nt][1] = fmaf((float)c[mt][nt][1], s1, f[mt][nt][1]);
                    f[mt][nt][2] = fmaf((float)c[mt][nt][2], s0, f[mt][nt][2]);
                    f[mt][nt][3] = fmaf((float)c[mt][nt][3], s1, f[mt][nt][3]);
                    c[mt][nt][0] = c[mt][nt][1] = c[mt][nt][2] = c[mt][nt][3] = 0;
                }
            }
        }
    }

    // epilogue: out[m,o] = sx[m]*(f - zp[m]*Wsum[o])
#pragma unroll
    for (int mt = 0; mt < 4; ++mt) {
        int rlo = bm * BM + warpm * 64 + mt * 16 + gid;
        int rhi = rlo + 8;
        float sxl = g_sx[rlo], zl = g_zp[rlo];
        float sxh = g_sx[rhi], zh = g_zp[rhi];
#pragma unroll
        for (int nt = 0; nt < 4; ++nt) {
            int o0 = bn * BN + warpn * 32 + nt * 8 + tig * 2;
            float w0 = g_wsum[o0], w1 = g_wsum[o0 + 1];
            float2 vlo = make_float2(sxl * (f[mt][nt][0] - zl * w0),
                                     sxl * (f[mt][nt][1] - zl * w1));
            float2 vhi = make_float2(sxh * (f[mt][nt][2] - zh * w0),
                                     sxh * (f[mt][nt][3] - zh * w1));
            *reinterpret_cast<float2*>(out + (size_t)rlo * N_OUT + o0) = vlo;
            *reinterpret_cast<float2*>(out + (size_t)rhi * N_OUT + o0) = vhi;
        }
    }
}

// ============================================================================
// launch
// ============================================================================
extern "C" void kernel_launch(void* const* d_in, const int* in_sizes, int n_in,
                              void* d_out, int out_size) {
    const float* x      = (const float*)d_in[0];
    const int*   w      = (const int*)d_in[1];     // int8 upcast to int32 by harness
    const float* scales = (const float*)d_in[2];
    const float* zeros  = (const float*)d_in[3];
    float* out = (float*)d_out;

    cudaFuncSetAttribute(gemm_kernel, cudaFuncAttributeMaxDynamicSharedMemorySize, SMEM_DYN);

    quant_kernel<<<M_TOK, 256>>>(x);
    wprep_kernel<<<N_OUT, 256>>>(w, scales, zeros);
    gemm_kernel<<<dim3(N_OUT / BN, M_TOK / BM), 256, SMEM_DYN>>>(scales, out);
}

// round 5
// speedup vs baseline: 2.6959x; 2.6959x over previous
#include <cuda_runtime.h>
#include <cuda_fp16.h>
#include <cstdint>

#define M_TOK 8192
#define K_DIM 4096
#define N_OUT 4096
#define NGRP  16
#define KB2   (K_DIM * 2)               // row stride in bytes (fp16)

// ---- scratch (device globals; no allocation allowed) ----
__device__ __align__(16) __half g_a16[(size_t)M_TOK * K_DIM];   // fp16(q - zp), exact ints
__device__ __align__(16) __half g_b16[(size_t)N_OUT * K_DIM];   // fp16((w - z) * s)
__device__ float g_sx[M_TOK];                                    // per-token scale

// ============================================================================
// Kernel 1: per-token quant; writes A = fp16(q - zp) (exact integers)
// ============================================================================
__global__ __launch_bounds__(256) void quant_kernel(const float* __restrict__ x) {
    int row = blockIdx.x;
    int tid = threadIdx.x;
    const float4* xr4 = reinterpret_cast<const float4*>(x + (size_t)row * K_DIM) + tid * 4;

    float4 v[4];
#pragma unroll
    for (int i = 0; i < 4; i++) v[i] = xr4[i];

    float mn = 0.0f, mx = 0.0f;
#pragma unroll
    for (int i = 0; i < 4; i++) {
        mn = fminf(mn, fminf(fminf(v[i].x, v[i].y), fminf(v[i].z, v[i].w)));
        mx = fmaxf(mx, fmaxf(fmaxf(v[i].x, v[i].y), fmaxf(v[i].z, v[i].w)));
    }
#pragma unroll
    for (int off = 16; off; off >>= 1) {
        mn = fminf(mn, __shfl_xor_sync(0xffffffffu, mn, off));
        mx = fmaxf(mx, __shfl_xor_sync(0xffffffffu, mx, off));
    }
    __shared__ float smn[8], smx[8];
    if ((tid & 31) == 0) { smn[tid >> 5] = mn; smx[tid >> 5] = mx; }
    __syncthreads();
    mn = smn[0]; mx = smx[0];
#pragma unroll
    for (int i = 1; i < 8; i++) { mn = fminf(mn, smn[i]); mx = fmaxf(mx, smx[i]); }

    float scale = fmaxf((mx - mn) / 255.0f, 1.1920928955078125e-07f);
    float a = mn / scale, b = mx / scale;
    float t = (-128.0f + a) + (127.0f + b);
    float zp0 = (t > 0.0f) ? (-128.0f - a) : (127.0f - b);
    float zpf = fminf(fmaxf(rintf(zp0), -128.0f), 127.0f);

    const float* pv = reinterpret_cast<const float*>(v);
    uint32_t packed[8];
#pragma unroll
    for (int j = 0; j < 8; j++) {
        float q0 = fminf(fmaxf(rintf(pv[2 * j] / scale) + zpf, -128.0f), 127.0f);
        float q1 = fminf(fmaxf(rintf(pv[2 * j + 1] / scale) + zpf, -128.0f), 127.0f);
        __half2 h = __floats2half2_rn(q0 - zpf, q1 - zpf);   // exact ints in [-255,255]
        packed[j] = *reinterpret_cast<uint32_t*>(&h);
    }
    uint4* dst = reinterpret_cast<uint4*>(g_a16 + (size_t)row * K_DIM + tid * 16);
    dst[0] = make_uint4(packed[0], packed[1], packed[2], packed[3]);
    dst[1] = make_uint4(packed[4], packed[5], packed[6], packed[7]);
    if (tid == 0) g_sx[row] = scale;
}

// ============================================================================
// Kernel 2: weight dequant to fp16 — B = fp16((w - z) * s). W arrives as int32.
// ============================================================================
__global__ __launch_bounds__(256) void wprep_kernel(const int* __restrict__ W,
                                                    const float* __restrict__ scales,
                                                    const float* __restrict__ zeros) {
    int o = blockIdx.x;
    int tid = threadIdx.x;
    int g = tid >> 4;
    float z = zeros[o * NGRP + g];
    float s = scales[o * NGRP + g];

    const int4* Wrow = reinterpret_cast<const int4*>(W + (size_t)o * K_DIM) + tid * 4;
    uint32_t packed[8];
#pragma unroll
    for (int c = 0; c < 4; c++) {
        int4 w4 = Wrow[c];
        __half2 h0 = __floats2half2_rn(((float)w4.x - z) * s, ((float)w4.y - z) * s);
        __half2 h1 = __floats2half2_rn(((float)w4.z - z) * s, ((float)w4.w - z) * s);
        packed[2 * c]     = *reinterpret_cast<uint32_t*>(&h0);
        packed[2 * c + 1] = *reinterpret_cast<uint32_t*>(&h1);
    }
    uint4* dst = reinterpret_cast<uint4*>(g_b16 + (size_t)o * K_DIM + tid * 16);
    dst[0] = make_uint4(packed[0], packed[1], packed[2], packed[3]);
    dst[1] = make_uint4(packed[4], packed[5], packed[6], packed[7]);
}

// ============================================================================
// Kernel 3: pipelined fp16 HMMA GEMM (cp.async 4-stage, ldmatrix)
// ============================================================================
#define BM 128
#define BN 128
#define BKH 64                            // K halves per stage (128 bytes/row)
#define NSTAGE 4
#define TILE_B (BM * 128)                 // 16384 bytes per tile (A or B)
#define STAGE_B (2 * TILE_B)              // 32768
#define SMEM_DYN (NSTAGE * STAGE_B + 1024)
#define KITERS (K_DIM / BKH)              // 64

__device__ __forceinline__ uint32_t s2u(const void* p) {
    uint32_t a;
    asm("{ .reg .u64 t; cvta.to.shared.u64 t, %1; cvt.u32.u64 %0, t; }" : "=r"(a) : "l"(p));
    return a;
}
// tile-local swizzled offset: 128-byte rows, SW128
__device__ __forceinline__ uint32_t swz(uint32_t r, uint32_t c16) {
    uint32_t off = r * 128 + c16 * 16;
    return off ^ ((off >> 3) & 0x70);
}
__device__ __forceinline__ void ldsm4(uint32_t& d0, uint32_t& d1, uint32_t& d2, uint32_t& d3,
                                      uint32_t addr) {
    asm volatile("ldmatrix.sync.aligned.m8n8.x4.shared.b16 {%0,%1,%2,%3}, [%4];"
                 : "=r"(d0), "=r"(d1), "=r"(d2), "=r"(d3) : "r"(addr));
}
__device__ __forceinline__ void mma_f16(float& c0, float& c1, float& c2, float& c3,
                                        uint32_t a0, uint32_t a1, uint32_t a2, uint32_t a3,
                                        uint32_t b0, uint32_t b1) {
    asm volatile(
        "mma.sync.aligned.m16n8k16.row.col.f32.f16.f16.f32 "
        "{%0,%1,%2,%3}, {%4,%5,%6,%7}, {%8,%9}, {%0,%1,%2,%3};\n"
        : "+f"(c0), "+f"(c1), "+f"(c2), "+f"(c3)
        : "r"(a0), "r"(a1), "r"(a2), "r"(a3), "r"(b0), "r"(b1));
}

__global__ __launch_bounds__(256, 1) void gemm_kernel(float* __restrict__ out) {
    extern __shared__ char smem_raw[];
    char* sm = (char*)(((uintptr_t)smem_raw + 1023) & ~(uintptr_t)1023);
    uint32_t sbase = s2u(sm);

    int tid = threadIdx.x, lane = tid & 31, wid = tid >> 5;
    int warpm = wid & 1, warpn = wid >> 1;        // 2 x 4 warp grid, warp tile 64x32
    int gid = lane >> 2, tig = lane & 3;
    int bn = blockIdx.x, bm = blockIdx.y;

    // per-lane ldmatrix swizzled offsets (tile-local), proven mapping from R4
    uint32_t aoff[4][4], boff[2][4];
    {
        int g8 = lane >> 3, rin = lane & 7;
#pragma unroll
        for (int mt = 0; mt < 4; mt++)
#pragma unroll
            for (int ks = 0; ks < 4; ks++)
                aoff[mt][ks] = swz(warpm * 64 + mt * 16 + (g8 & 1) * 8 + rin, ks * 2 + (g8 >> 1));
#pragma unroll
        for (int p = 0; p < 2; p++)
#pragma unroll
            for (int ks = 0; ks < 4; ks++)
                boff[p][ks] = swz(warpn * 32 + p * 16 + (g8 >> 1) * 8 + rin, ks * 2 + (g8 & 1));
    }

    const char* Ag = (const char*)g_a16 + (size_t)bm * BM * KB2;
    const char* Bg = (const char*)g_b16 + (size_t)bn * BN * KB2;

    // per-thread cp.async assignments: 4 x 16B chunks per tile per thread
    uint32_t sa_off[4], sb_off[4];
    const char* ga_ptr[4];
    const char* gb_ptr[4];
#pragma unroll
    for (int i = 0; i < 4; i++) {
        int seg = tid + i * 256;                  // 0..1023
        int r = seg >> 3, c16 = seg & 7;
        sa_off[i] = swz(r, c16);
        sb_off[i] = TILE_B + sa_off[i];
        ga_ptr[i] = Ag + (size_t)r * KB2 + c16 * 16;
        gb_ptr[i] = Bg + (size_t)r * KB2 + c16 * 16;
    }

#define ISSUE(kc)                                                                        \
    {                                                                                    \
        uint32_t st = sbase + ((kc) & 3) * STAGE_B;                                      \
        _Pragma("unroll") for (int i = 0; i < 4; i++) {                                  \
            asm volatile("cp.async.cg.shared.global [%0], [%1], 16;"                     \
                         :: "r"(st + sa_off[i]), "l"(ga_ptr[i] + (kc) * 128) : "memory"); \
            asm volatile("cp.async.cg.shared.global [%0], [%1], 16;"                     \
                         :: "r"(st + sb_off[i]), "l"(gb_ptr[i] + (kc) * 128) : "memory"); \
        }                                                                                \
    }

    float c[4][4][4];
#pragma unroll
    for (int mt = 0; mt < 4; mt++)
#pragma unroll
        for (int nt = 0; nt < 4; nt++)
#pragma unroll
            for (int r = 0; r < 4; r++) c[mt][nt][r] = 0.0f;

    // prologue: fill 3 stages
#pragma unroll
    for (int s = 0; s < NSTAGE - 1; s++) {
        ISSUE(s);
        asm volatile("cp.async.commit_group;" ::: "memory");
    }

    for (int kc = 0; kc < KITERS; ++kc) {
        asm volatile("cp.async.wait_group 2;" ::: "memory");
        __syncthreads();

        if (kc + NSTAGE - 1 < KITERS) ISSUE(kc + NSTAGE - 1);
        asm volatile("cp.async.commit_group;" ::: "memory");

        uint32_t sA = sbase + (kc & 3) * STAGE_B;
        uint32_t sB = sA + TILE_B;
#pragma unroll
        for (int ks = 0; ks < 4; ks++) {
            uint32_t a[4][4], b[2][4];
#pragma unroll
            for (int mt = 0; mt < 4; mt++)
                ldsm4(a[mt][0], a[mt][1], a[mt][2], a[mt][3], sA + aoff[mt][ks]);
#pragma unroll
            for (int p = 0; p < 2; p++)
                ldsm4(b[p][0], b[p][1], b[p][2], b[p][3], sB + boff[p][ks]);
#pragma unroll
            for (int mt = 0; mt < 4; mt++)
#pragma unroll
                for (int nt = 0; nt < 4; nt++)
                    mma_f16(c[mt][nt][0], c[mt][nt][1], c[mt][nt][2], c[mt][nt][3],
                            a[mt][0], a[mt][1], a[mt][2], a[mt][3],
                            b[nt >> 1][(nt & 1) * 2], b[nt >> 1][(nt & 1) * 2 + 1]);
        }
    }

    // epilogue: out[m,o] = sx[m] * acc  (B already carries weight scales)
#pragma unroll
    for (int mt = 0; mt < 4; ++mt) {
        int rlo = bm * BM + warpm * 64 + mt * 16 + gid;
        int rhi = rlo + 8;
        float sxl = g_sx[rlo];
        float sxh = g_sx[rhi];
#pragma unroll
        for (int nt = 0; nt < 4; ++nt) {
            int o0 = bn * BN + warpn * 32 + nt * 8 + tig * 2;
            float2 vlo = make_float2(sxl * c[mt][nt][0], sxl * c[mt][nt][1]);
            float2 vhi = make_float2(sxh * c[mt][nt][2], sxh * c[mt][nt][3]);
            *reinterpret_cast<float2*>(out + (size_t)rlo * N_OUT + o0) = vlo;
            *reinterpret_cast<float2*>(out + (size_t)rhi * N_OUT + o0) = vhi;
        }
    }
}

// ============================================================================
// launch
// ============================================================================
extern "C" void kernel_launch(void* const* d_in, const int* in_sizes, int n_in,
                              void* d_out, int out_size) {
    const float* x      = (const float*)d_in[0];
    const int*   w      = (const int*)d_in[1];     // int8 upcast to int32 by harness
    const float* scales = (const float*)d_in[2];
    const float* zeros  = (const float*)d_in[3];
    float* out = (float*)d_out;

    cudaFuncSetAttribute(gemm_kernel, cudaFuncAttributeMaxDynamicSharedMemorySize, SMEM_DYN);

    quant_kernel<<<M_TOK, 256>>>(x);
    wprep_kernel<<<N_OUT, 256>>>(w, scales, zeros);
    gemm_kernel<<<dim3(N_OUT / BN, M_TOK / BM), 256, SMEM_DYN>>>(out);
}

// round 6
// speedup vs baseline: 2.9012x; 1.0762x over previous
#include <cuda_runtime.h>
#include <cuda_fp16.h>
#include <cstdint>

#define M_TOK 8192
#define K_DIM 4096
#define N_OUT 4096
#define NGRP  16
#define KB2   (K_DIM * 2)               // row stride in bytes (fp16)

// ---- scratch (device globals; no allocation allowed) ----
__device__ __align__(16) __half g_a16[(size_t)M_TOK * K_DIM];   // fp16(q - zp), exact ints
__device__ __align__(16) __half g_b16[(size_t)N_OUT * K_DIM];   // fp16((w - z) * s)
__device__ float g_sx[M_TOK];                                    // per-token scale

// ============================================================================
// Kernel 1: per-token quant; writes A = fp16(q - zp) (exact integers)
// ============================================================================
__global__ __launch_bounds__(256) void quant_kernel(const float* __restrict__ x) {
    int row = blockIdx.x;
    int tid = threadIdx.x;
    const float4* xr4 = reinterpret_cast<const float4*>(x + (size_t)row * K_DIM) + tid * 4;

    float4 v[4];
#pragma unroll
    for (int i = 0; i < 4; i++) v[i] = xr4[i];

    float mn = 0.0f, mx = 0.0f;
#pragma unroll
    for (int i = 0; i < 4; i++) {
        mn = fminf(mn, fminf(fminf(v[i].x, v[i].y), fminf(v[i].z, v[i].w)));
        mx = fmaxf(mx, fmaxf(fmaxf(v[i].x, v[i].y), fmaxf(v[i].z, v[i].w)));
    }
#pragma unroll
    for (int off = 16; off; off >>= 1) {
        mn = fminf(mn, __shfl_xor_sync(0xffffffffu, mn, off));
        mx = fmaxf(mx, __shfl_xor_sync(0xffffffffu, mx, off));
    }
    __shared__ float smn[8], smx[8];
    if ((tid & 31) == 0) { smn[tid >> 5] = mn; smx[tid >> 5] = mx; }
    __syncthreads();
    mn = smn[0]; mx = smx[0];
#pragma unroll
    for (int i = 1; i < 8; i++) { mn = fminf(mn, smn[i]); mx = fmaxf(mx, smx[i]); }

    float scale = fmaxf((mx - mn) / 255.0f, 1.1920928955078125e-07f);
    float a = mn / scale, b = mx / scale;
    float t = (-128.0f + a) + (127.0f + b);
    float zp0 = (t > 0.0f) ? (-128.0f - a) : (127.0f - b);
    float zpf = fminf(fmaxf(rintf(zp0), -128.0f), 127.0f);

    const float* pv = reinterpret_cast<const float*>(v);
    uint32_t packed[8];
#pragma unroll
    for (int j = 0; j < 8; j++) {
        float q0 = fminf(fmaxf(rintf(pv[2 * j] / scale) + zpf, -128.0f), 127.0f);
        float q1 = fminf(fmaxf(rintf(pv[2 * j + 1] / scale) + zpf, -128.0f), 127.0f);
        __half2 h = __floats2half2_rn(q0 - zpf, q1 - zpf);   // exact ints in [-255,255]
        packed[j] = *reinterpret_cast<uint32_t*>(&h);
    }
    uint4* dst = reinterpret_cast<uint4*>(g_a16 + (size_t)row * K_DIM + tid * 16);
    dst[0] = make_uint4(packed[0], packed[1], packed[2], packed[3]);
    dst[1] = make_uint4(packed[4], packed[5], packed[6], packed[7]);
    if (tid == 0) g_sx[row] = scale;
}

// ============================================================================
// Kernel 2: weight dequant to fp16 — B = fp16((w - z) * s). W arrives as int32.
// ============================================================================
__global__ __launch_bounds__(256) void wprep_kernel(const int* __restrict__ W,
                                                    const float* __restrict__ scales,
                                                    const float* __restrict__ zeros) {
    int o = blockIdx.x;
    int tid = threadIdx.x;
    int g = tid >> 4;
    float z = zeros[o * NGRP + g];
    float s = scales[o * NGRP + g];

    const int4* Wrow = reinterpret_cast<const int4*>(W + (size_t)o * K_DIM) + tid * 4;
    uint32_t packed[8];
#pragma unroll
    for (int c = 0; c < 4; c++) {
        int4 w4 = Wrow[c];
        __half2 h0 = __floats2half2_rn(((float)w4.x - z) * s, ((float)w4.y - z) * s);
        __half2 h1 = __floats2half2_rn(((float)w4.z - z) * s, ((float)w4.w - z) * s);
        packed[2 * c]     = *reinterpret_cast<uint32_t*>(&h0);
        packed[2 * c + 1] = *reinterpret_cast<uint32_t*>(&h1);
    }
    uint4* dst = reinterpret_cast<uint4*>(g_b16 + (size_t)o * K_DIM + tid * 16);
    dst[0] = make_uint4(packed[0], packed[1], packed[2], packed[3]);
    dst[1] = make_uint4(packed[4], packed[5], packed[6], packed[7]);
}

// ============================================================================
// Kernel 3: pipelined fp16 HMMA GEMM — 128x256 block, 64x64 warp tiles
// ============================================================================
#define BM 128
#define BN 256
#define BKH 64                            // K halves per stage (128 bytes/row)
#define NSTAGE 3
#define A_TILE (BM * 128)                 // 16384 bytes
#define B_TILE (BN * 128)                 // 32768 bytes
#define STAGE_B (A_TILE + B_TILE)         // 49152
#define SMEM_DYN (NSTAGE * STAGE_B + 1024)
#define KITERS (K_DIM / BKH)              // 64

__device__ __forceinline__ uint32_t s2u(const void* p) {
    uint32_t a;
    asm("{ .reg .u64 t; cvta.to.shared.u64 t, %1; cvt.u32.u64 %0, t; }" : "=r"(a) : "l"(p));
    return a;
}
// tile-local swizzled offset: 128-byte rows, SW128
__device__ __forceinline__ uint32_t swz(uint32_t r, uint32_t c16) {
    uint32_t off = r * 128 + c16 * 16;
    return off ^ ((off >> 3) & 0x70);
}
__device__ __forceinline__ void ldsm4(uint32_t& d0, uint32_t& d1, uint32_t& d2, uint32_t& d3,
                                      uint32_t addr) {
    asm volatile("ldmatrix.sync.aligned.m8n8.x4.shared.b16 {%0,%1,%2,%3}, [%4];"
                 : "=r"(d0), "=r"(d1), "=r"(d2), "=r"(d3) : "r"(addr));
}
__device__ __forceinline__ void mma_f16(float& c0, float& c1, float& c2, float& c3,
                                        uint32_t a0, uint32_t a1, uint32_t a2, uint32_t a3,
                                        uint32_t b0, uint32_t b1) {
    asm volatile(
        "mma.sync.aligned.m16n8k16.row.col.f32.f16.f16.f32 "
        "{%0,%1,%2,%3}, {%4,%5,%6,%7}, {%8,%9}, {%0,%1,%2,%3};\n"
        : "+f"(c0), "+f"(c1), "+f"(c2), "+f"(c3)
        : "r"(a0), "r"(a1), "r"(a2), "r"(a3), "r"(b0), "r"(b1));
}

__global__ __launch_bounds__(256, 1) void gemm_kernel(float* __restrict__ out) {
    extern __shared__ char smem_raw[];
    char* sm = (char*)(((uintptr_t)smem_raw + 1023) & ~(uintptr_t)1023);
    uint32_t sbase = s2u(sm);

    int tid = threadIdx.x, lane = tid & 31, wid = tid >> 5;
    int warpm = wid & 1, warpn = wid >> 1;        // 2 x 4 warp grid, warp tile 64x64
    int gid = lane >> 2, tig = lane & 3;
    int bn = blockIdx.x, bm = blockIdx.y;

    // per-lane ldmatrix swizzled offsets (tile-local); proven mapping
    uint32_t aoff[4][4], boff[4][4];
    {
        int g8 = lane >> 3, rin = lane & 7;
#pragma unroll
        for (int mt = 0; mt < 4; mt++)
#pragma unroll
            for (int ks = 0; ks < 4; ks++)
                aoff[mt][ks] = swz(warpm * 64 + mt * 16 + (g8 & 1) * 8 + rin, ks * 2 + (g8 >> 1));
#pragma unroll
        for (int p = 0; p < 4; p++)
#pragma unroll
            for (int ks = 0; ks < 4; ks++)
                boff[p][ks] = swz(warpn * 64 + p * 16 + (g8 >> 1) * 8 + rin, ks * 2 + (g8 & 1));
    }

    const char* Ag = (const char*)g_a16 + (size_t)bm * BM * KB2;
    const char* Bg = (const char*)g_b16 + (size_t)bn * BN * KB2;

    // per-thread cp.async assignments: A 4 chunks, B 8 chunks of 16B
    uint32_t sa_off[4], sb_off[8];
    const char* ga_ptr[4];
    const char* gb_ptr[8];
#pragma unroll
    for (int i = 0; i < 4; i++) {
        int seg = tid + i * 256;                  // 0..1023
        int r = seg >> 3, c16 = seg & 7;
        sa_off[i] = swz(r, c16);
        ga_ptr[i] = Ag + (size_t)r * KB2 + c16 * 16;
    }
#pragma unroll
    for (int i = 0; i < 8; i++) {
        int seg = tid + i * 256;                  // 0..2047
        int r = seg >> 3, c16 = seg & 7;
        sb_off[i] = A_TILE + swz(r, c16);
        gb_ptr[i] = Bg + (size_t)r * KB2 + c16 * 16;
    }

#define ISSUE(kc)                                                                        \
    {                                                                                    \
        uint32_t st = sbase + ((kc) % NSTAGE) * STAGE_B;                                 \
        _Pragma("unroll") for (int i = 0; i < 4; i++)                                    \
            asm volatile("cp.async.cg.shared.global [%0], [%1], 16;"                     \
                         :: "r"(st + sa_off[i]), "l"(ga_ptr[i] + (kc) * 128) : "memory"); \
        _Pragma("unroll") for (int i = 0; i < 8; i++)                                    \
            asm volatile("cp.async.cg.shared.global [%0], [%1], 16;"                     \
                         :: "r"(st + sb_off[i]), "l"(gb_ptr[i] + (kc) * 128) : "memory"); \
    }

    float c[4][8][4];
#pragma unroll
    for (int mt = 0; mt < 4; mt++)
#pragma unroll
        for (int nt = 0; nt < 8; nt++)
#pragma unroll
            for (int r = 0; r < 4; r++) c[mt][nt][r] = 0.0f;

    // prologue: fill 2 stages
#pragma unroll
    for (int s = 0; s < NSTAGE - 1; s++) {
        ISSUE(s);
        asm volatile("cp.async.commit_group;" ::: "memory");
    }

    for (int kc = 0; kc < KITERS; ++kc) {
        asm volatile("cp.async.wait_group 1;" ::: "memory");
        __syncthreads();

        if (kc + NSTAGE - 1 < KITERS) ISSUE(kc + NSTAGE - 1);
        asm volatile("cp.async.commit_group;" ::: "memory");

        uint32_t sA = sbase + (kc % NSTAGE) * STAGE_B;
        uint32_t sB = sA;   // boff already includes nothing; B base is sA + A_TILE via boff? no:
#pragma unroll
        for (int ks = 0; ks < 4; ks++) {
            uint32_t a[4][4], b[4][4];
#pragma unroll
            for (int mt = 0; mt < 4; mt++)
                ldsm4(a[mt][0], a[mt][1], a[mt][2], a[mt][3], sA + aoff[mt][ks]);
#pragma unroll
            for (int p = 0; p < 4; p++)
                ldsm4(b[p][0], b[p][1], b[p][2], b[p][3], sA + A_TILE + boff[p][ks]);
#pragma unroll
            for (int mt = 0; mt < 4; mt++)
#pragma unroll
                for (int nt = 0; nt < 8; nt++)
                    mma_f16(c[mt][nt][0], c[mt][nt][1], c[mt][nt][2], c[mt][nt][3],
                            a[mt][0], a[mt][1], a[mt][2], a[mt][3],
                            b[nt >> 1][(nt & 1) * 2], b[nt >> 1][(nt & 1) * 2 + 1]);
        }
        (void)sB;
    }

    // epilogue: out[m,o] = sx[m] * acc  (B already carries weight scales)
#pragma unroll
    for (int mt = 0; mt < 4; ++mt) {
        int rlo = bm * BM + warpm * 64 + mt * 16 + gid;
        int rhi = rlo + 8;
        float sxl = g_sx[rlo];
        float sxh = g_sx[rhi];
#pragma unroll
        for (int nt = 0; nt < 8; ++nt) {
            int o0 = bn * BN + warpn * 64 + nt * 8 + tig * 2;
            float2 vlo = make_float2(sxl * c[mt][nt][0], sxl * c[mt][nt][1]);
            float2 vhi = make_float2(sxh * c[mt][nt][2], sxh * c[mt][nt][3]);
            *reinterpret_cast<float2*>(out + (size_t)rlo * N_OUT + o0) = vlo;
            *reinterpret_cast<float2*>(out + (size_t)rhi * N_OUT + o0) = vhi;
        }
    }
}

// ============================================================================
// launch
// ============================================================================
extern "C" void kernel_launch(void* const* d_in, const int* in_sizes, int n_in,
                              void* d_out, int out_size) {
    const float* x      = (const float*)d_in[0];
    const int*   w      = (const int*)d_in[1];     // int8 upcast to int32 by harness
    const float* scales = (const float*)d_in[2];
    const float* zeros  = (const float*)d_in[3];
    float* out = (float*)d_out;

    cudaFuncSetAttribute(gemm_kernel, cudaFuncAttributeMaxDynamicSharedMemorySize, SMEM_DYN);

    quant_kernel<<<M_TOK, 256>>>(x);
    wprep_kernel<<<N_OUT, 256>>>(w, scales, zeros);
    gemm_kernel<<<dim3(N_OUT / BN, M_TOK / BM), 256, SMEM_DYN>>>(out);
}

// round 7
// speedup vs baseline: 3.0847x; 1.0632x over previous
#include <cuda_runtime.h>
#include <cuda_fp16.h>
#include <cstdint>

#define M_TOK 8192
#define K_DIM 4096
#define N_OUT 4096
#define NGRP  16
#define KB2   (K_DIM * 2)               // row stride in bytes (fp16)

// ---- scratch (device globals; no allocation allowed) ----
__device__ __align__(16) __half g_a16[(size_t)M_TOK * K_DIM];   // fp16(q - zp), exact ints
__device__ __align__(16) __half g_b16[(size_t)N_OUT * K_DIM];   // fp16((w - z) * s)
__device__ float g_sx[M_TOK];                                    // per-token scale

// ============================================================================
// Kernel 1: per-token quant; writes A = fp16(q - zp) (exact integers)
// ============================================================================
__global__ __launch_bounds__(256) void quant_kernel(const float* __restrict__ x) {
    int row = blockIdx.x;
    int tid = threadIdx.x;
    const float4* xr4 = reinterpret_cast<const float4*>(x + (size_t)row * K_DIM) + tid * 4;

    float4 v[4];
#pragma unroll
    for (int i = 0; i < 4; i++) v[i] = xr4[i];

    float mn = 0.0f, mx = 0.0f;
#pragma unroll
    for (int i = 0; i < 4; i++) {
        mn = fminf(mn, fminf(fminf(v[i].x, v[i].y), fminf(v[i].z, v[i].w)));
        mx = fmaxf(mx, fmaxf(fmaxf(v[i].x, v[i].y), fmaxf(v[i].z, v[i].w)));
    }
#pragma unroll
    for (int off = 16; off; off >>= 1) {
        mn = fminf(mn, __shfl_xor_sync(0xffffffffu, mn, off));
        mx = fmaxf(mx, __shfl_xor_sync(0xffffffffu, mx, off));
    }
    __shared__ float smn[8], smx[8];
    if ((tid & 31) == 0) { smn[tid >> 5] = mn; smx[tid >> 5] = mx; }
    __syncthreads();
    mn = smn[0]; mx = smx[0];
#pragma unroll
    for (int i = 1; i < 8; i++) { mn = fminf(mn, smn[i]); mx = fmaxf(mx, smx[i]); }

    float scale = fmaxf((mx - mn) / 255.0f, 1.1920928955078125e-07f);
    float a = mn / scale, b = mx / scale;
    float t = (-128.0f + a) + (127.0f + b);
    float zp0 = (t > 0.0f) ? (-128.0f - a) : (127.0f - b);
    float zpf = fminf(fmaxf(rintf(zp0), -128.0f), 127.0f);

    const float* pv = reinterpret_cast<const float*>(v);
    uint32_t packed[8];
#pragma unroll
    for (int j = 0; j < 8; j++) {
        float q0 = fminf(fmaxf(rintf(pv[2 * j] / scale) + zpf, -128.0f), 127.0f);
        float q1 = fminf(fmaxf(rintf(pv[2 * j + 1] / scale) + zpf, -128.0f), 127.0f);
        __half2 h = __floats2half2_rn(q0 - zpf, q1 - zpf);   // exact ints in [-255,255]
        packed[j] = *reinterpret_cast<uint32_t*>(&h);
    }
    uint4* dst = reinterpret_cast<uint4*>(g_a16 + (size_t)row * K_DIM + tid * 16);
    dst[0] = make_uint4(packed[0], packed[1], packed[2], packed[3]);
    dst[1] = make_uint4(packed[4], packed[5], packed[6], packed[7]);
    if (tid == 0) g_sx[row] = scale;
}

// ============================================================================
// Kernel 2: weight dequant to fp16 — B = fp16((w - z) * s). W arrives as int32.
// ============================================================================
__global__ __launch_bounds__(256) void wprep_kernel(const int* __restrict__ W,
                                                    const float* __restrict__ scales,
                                                    const float* __restrict__ zeros) {
    int o = blockIdx.x;
    int tid = threadIdx.x;
    int g = tid >> 4;
    float z = zeros[o * NGRP + g];
    float s = scales[o * NGRP + g];

    const int4* Wrow = reinterpret_cast<const int4*>(W + (size_t)o * K_DIM) + tid * 4;
    uint32_t packed[8];
#pragma unroll
    for (int c = 0; c < 4; c++) {
        int4 w4 = Wrow[c];
        __half2 h0 = __floats2half2_rn(((float)w4.x - z) * s, ((float)w4.y - z) * s);
        __half2 h1 = __floats2half2_rn(((float)w4.z - z) * s, ((float)w4.w - z) * s);
        packed[2 * c]     = *reinterpret_cast<uint32_t*>(&h0);
        packed[2 * c + 1] = *reinterpret_cast<uint32_t*>(&h1);
    }
    uint4* dst = reinterpret_cast<uint4*>(g_b16 + (size_t)o * K_DIM + tid * 16);
    dst[0] = make_uint4(packed[0], packed[1], packed[2], packed[3]);
    dst[1] = make_uint4(packed[4], packed[5], packed[6], packed[7]);
}

// ============================================================================
// Kernel 3: pipelined fp16 HMMA GEMM — 128x256 block, 64x64 warp tiles,
//           4-stage cp.async + intra-iteration fragment double-buffering
// ============================================================================
#define BM 128
#define BN 256
#define BKH 64                            // K halves per stage (128 bytes/row)
#define NSTAGE 4
#define A_TILE (BM * 128)                 // 16384 bytes
#define B_TILE (BN * 128)                 // 32768 bytes
#define STAGE_B (A_TILE + B_TILE)         // 49152
#define SMEM_DYN (NSTAGE * STAGE_B + 1024)
#define KITERS (K_DIM / BKH)              // 64

__device__ __forceinline__ uint32_t s2u(const void* p) {
    uint32_t a;
    asm("{ .reg .u64 t; cvta.to.shared.u64 t, %1; cvt.u32.u64 %0, t; }" : "=r"(a) : "l"(p));
    return a;
}
// tile-local swizzled offset: 128-byte rows, SW128
__device__ __forceinline__ uint32_t swz(uint32_t r, uint32_t c16) {
    uint32_t off = r * 128 + c16 * 16;
    return off ^ ((off >> 3) & 0x70);
}
__device__ __forceinline__ void ldsm4(uint32_t& d0, uint32_t& d1, uint32_t& d2, uint32_t& d3,
                                      uint32_t addr) {
    asm volatile("ldmatrix.sync.aligned.m8n8.x4.shared.b16 {%0,%1,%2,%3}, [%4];"
                 : "=r"(d0), "=r"(d1), "=r"(d2), "=r"(d3) : "r"(addr));
}
__device__ __forceinline__ void mma_f16(float& c0, float& c1, float& c2, float& c3,
                                        uint32_t a0, uint32_t a1, uint32_t a2, uint32_t a3,
                                        uint32_t b0, uint32_t b1) {
    asm volatile(
        "mma.sync.aligned.m16n8k16.row.col.f32.f16.f16.f32 "
        "{%0,%1,%2,%3}, {%4,%5,%6,%7}, {%8,%9}, {%0,%1,%2,%3};\n"
        : "+f"(c0), "+f"(c1), "+f"(c2), "+f"(c3)
        : "r"(a0), "r"(a1), "r"(a2), "r"(a3), "r"(b0), "r"(b1));
}

__global__ __launch_bounds__(256, 1) void gemm_kernel(float* __restrict__ out) {
    extern __shared__ char smem_raw[];
    char* sm = (char*)(((uintptr_t)smem_raw + 1023) & ~(uintptr_t)1023);
    uint32_t sbase = s2u(sm);

    int tid = threadIdx.x, lane = tid & 31, wid = tid >> 5;
    int warpm = wid & 1, warpn = wid >> 1;        // 2 x 4 warp grid, warp tile 64x64
    int gid = lane >> 2, tig = lane & 3;
    int bn = blockIdx.x, bm = blockIdx.y;

    // per-lane ldmatrix swizzled offsets (tile-local); proven mapping
    uint32_t aoff[4][4], boff[4][4];
    {
        int g8 = lane >> 3, rin = lane & 7;
#pragma unroll
        for (int mt = 0; mt < 4; mt++)
#pragma unroll
            for (int ks = 0; ks < 4; ks++)
                aoff[mt][ks] = swz(warpm * 64 + mt * 16 + (g8 & 1) * 8 + rin, ks * 2 + (g8 >> 1));
#pragma unroll
        for (int p = 0; p < 4; p++)
#pragma unroll
            for (int ks = 0; ks < 4; ks++)
                boff[p][ks] = A_TILE + swz(warpn * 64 + p * 16 + (g8 >> 1) * 8 + rin, ks * 2 + (g8 & 1));
    }

    const char* Ag = (const char*)g_a16 + (size_t)bm * BM * KB2;
    const char* Bg = (const char*)g_b16 + (size_t)bn * BN * KB2;

    // per-thread cp.async assignments as 32-bit offsets (register diet)
    uint32_t sa_off[4], sb_off[8], ga_off[4], gb_off[8];
#pragma unroll
    for (int i = 0; i < 4; i++) {
        int seg = tid + i * 256;                  // 0..1023
        int r = seg >> 3, c16 = seg & 7;
        sa_off[i] = swz(r, c16);
        ga_off[i] = (uint32_t)(r * KB2 + c16 * 16);
    }
#pragma unroll
    for (int i = 0; i < 8; i++) {
        int seg = tid + i * 256;                  // 0..2047
        int r = seg >> 3, c16 = seg & 7;
        sb_off[i] = A_TILE + swz(r, c16);
        gb_off[i] = (uint32_t)(r * KB2 + c16 * 16);
    }

#define ISSUE(kc)                                                                            \
    {                                                                                        \
        uint32_t st = sbase + ((kc) & 3) * STAGE_B;                                          \
        uint32_t kb = (kc) * 128;                                                            \
        _Pragma("unroll") for (int i = 0; i < 4; i++)                                        \
            asm volatile("cp.async.cg.shared.global [%0], [%1], 16;"                         \
                         :: "r"(st + sa_off[i]), "l"(Ag + ga_off[i] + kb) : "memory");       \
        _Pragma("unroll") for (int i = 0; i < 8; i++)                                        \
            asm volatile("cp.async.cg.shared.global [%0], [%1], 16;"                         \
                         :: "r"(st + sb_off[i]), "l"(Bg + gb_off[i] + kb) : "memory");       \
    }

#define LOADFRAG(buf, sA, ks)                                                    \
    {                                                                            \
        _Pragma("unroll") for (int mt = 0; mt < 4; mt++)                         \
            ldsm4(a[buf][mt][0], a[buf][mt][1], a[buf][mt][2], a[buf][mt][3],    \
                  (sA) + aoff[mt][ks]);                                          \
        _Pragma("unroll") for (int p = 0; p < 4; p++)                            \
            ldsm4(b[buf][p][0], b[buf][p][1], b[buf][p][2], b[buf][p][3],        \
                  (sA) + boff[p][ks]);                                           \
    }

    float c[4][8][4];
#pragma unroll
    for (int mt = 0; mt < 4; mt++)
#pragma unroll
        for (int nt = 0; nt < 8; nt++)
#pragma unroll
            for (int r = 0; r < 4; r++) c[mt][nt][r] = 0.0f;

    uint32_t a[2][4][4], b[2][4][4];

    // prologue: fill 3 stages
#pragma unroll
    for (int s = 0; s < NSTAGE - 1; s++) {
        ISSUE(s);
        asm volatile("cp.async.commit_group;" ::: "memory");
    }

    for (int kc = 0; kc < KITERS; ++kc) {
        asm volatile("cp.async.wait_group 2;" ::: "memory");
        __syncthreads();

        if (kc + NSTAGE - 1 < KITERS) ISSUE(kc + NSTAGE - 1);
        asm volatile("cp.async.commit_group;" ::: "memory");

        uint32_t sA = sbase + (kc & 3) * STAGE_B;
        LOADFRAG(0, sA, 0);
#pragma unroll
        for (int ks = 0; ks < 4; ks++) {
            int cur = ks & 1;
            if (ks < 3) LOADFRAG(cur ^ 1, sA, ks + 1);
#pragma unroll
            for (int mt = 0; mt < 4; mt++)
#pragma unroll
                for (int nt = 0; nt < 8; nt++)
                    mma_f16(c[mt][nt][0], c[mt][nt][1], c[mt][nt][2], c[mt][nt][3],
                            a[cur][mt][0], a[cur][mt][1], a[cur][mt][2], a[cur][mt][3],
                            b[cur][nt >> 1][(nt & 1) * 2], b[cur][nt >> 1][(nt & 1) * 2 + 1]);
        }
    }

    // epilogue: out[m,o] = sx[m] * acc  (B already carries weight scales)
#pragma unroll
    for (int mt = 0; mt < 4; ++mt) {
        int rlo = bm * BM + warpm * 64 + mt * 16 + gid;
        int rhi = rlo + 8;
        float sxl = g_sx[rlo];
        float sxh = g_sx[rhi];
#pragma unroll
        for (int nt = 0; nt < 8; ++nt) {
            int o0 = bn * BN + warpn * 64 + nt * 8 + tig * 2;
            float2 vlo = make_float2(sxl * c[mt][nt][0], sxl * c[mt][nt][1]);
            float2 vhi = make_float2(sxh * c[mt][nt][2], sxh * c[mt][nt][3]);
            *reinterpret_cast<float2*>(out + (size_t)rlo * N_OUT + o0) = vlo;
            *reinterpret_cast<float2*>(out + (size_t)rhi * N_OUT + o0) = vhi;
        }
    }
}

// ============================================================================
// launch
// ============================================================================
extern "C" void kernel_launch(void* const* d_in, const int* in_sizes, int n_in,
                              void* d_out, int out_size) {
    const float* x      = (const float*)d_in[0];
    const int*   w      = (const int*)d_in[1];     // int8 upcast to int32 by harness
    const float* scales = (const float*)d_in[2];
    const float* zeros  = (const float*)d_in[3];
    float* out = (float*)d_out;

    cudaFuncSetAttribute(gemm_kernel, cudaFuncAttributeMaxDynamicSharedMemorySize, SMEM_DYN);

    quant_kernel<<<M_TOK, 256>>>(x);
    wprep_kernel<<<N_OUT, 256>>>(w, scales, zeros);
    gemm_kernel<<<dim3(N_OUT / BN, M_TOK / BM), 256, SMEM_DYN>>>(out);
}

// round 8
// speedup vs baseline: 3.3211x; 1.0766x over previous
#include <cuda_runtime.h>
#include <cuda_fp16.h>
#include <cstdint>

#define M_TOK 8192
#define K_DIM 4096
#define N_OUT 4096
#define NGRP  16
#define KB2   (K_DIM * 2)               // row stride in bytes (fp16)

// ---- scratch (device globals; no allocation allowed) ----
__device__ __align__(16) __half g_a16[(size_t)M_TOK * K_DIM];   // fp16(q - zp), exact ints
__device__ __align__(16) __half g_b16[(size_t)N_OUT * K_DIM];   // fp16((w - z) * s)
__device__ float g_sx[M_TOK];                                    // per-token scale

// ============================================================================
// Fused prep kernel: blocks [0,8192) do per-token quant -> g_a16,
//                    blocks [8192,12288) do weight dequant -> g_b16
// ============================================================================
__global__ __launch_bounds__(256) void prep_kernel(const float* __restrict__ x,
                                                   const int* __restrict__ W,
                                                   const float* __restrict__ scales,
                                                   const float* __restrict__ zeros) {
    int tid = threadIdx.x;
    if (blockIdx.x < M_TOK) {
        int row = blockIdx.x;
        const float4* xr4 = reinterpret_cast<const float4*>(x + (size_t)row * K_DIM) + tid * 4;

        float4 v[4];
#pragma unroll
        for (int i = 0; i < 4; i++) v[i] = xr4[i];

        float mn = 0.0f, mx = 0.0f;
#pragma unroll
        for (int i = 0; i < 4; i++) {
            mn = fminf(mn, fminf(fminf(v[i].x, v[i].y), fminf(v[i].z, v[i].w)));
            mx = fmaxf(mx, fmaxf(fmaxf(v[i].x, v[i].y), fmaxf(v[i].z, v[i].w)));
        }
#pragma unroll
        for (int off = 16; off; off >>= 1) {
            mn = fminf(mn, __shfl_xor_sync(0xffffffffu, mn, off));
            mx = fmaxf(mx, __shfl_xor_sync(0xffffffffu, mx, off));
        }
        __shared__ float smn[8], smx[8];
        if ((tid & 31) == 0) { smn[tid >> 5] = mn; smx[tid >> 5] = mx; }
        __syncthreads();
        mn = smn[0]; mx = smx[0];
#pragma unroll
        for (int i = 1; i < 8; i++) { mn = fminf(mn, smn[i]); mx = fmaxf(mx, smx[i]); }

        float scale = fmaxf((mx - mn) / 255.0f, 1.1920928955078125e-07f);
        float a = mn / scale, b = mx / scale;
        float t = (-128.0f + a) + (127.0f + b);
        float zp0 = (t > 0.0f) ? (-128.0f - a) : (127.0f - b);
        float zpf = fminf(fmaxf(rintf(zp0), -128.0f), 127.0f);

        const float* pv = reinterpret_cast<const float*>(v);
        uint32_t packed[8];
#pragma unroll
        for (int j = 0; j < 8; j++) {
            float q0 = fminf(fmaxf(rintf(pv[2 * j] / scale) + zpf, -128.0f), 127.0f);
            float q1 = fminf(fmaxf(rintf(pv[2 * j + 1] / scale) + zpf, -128.0f), 127.0f);
            __half2 h = __floats2half2_rn(q0 - zpf, q1 - zpf);   // exact ints in [-255,255]
            packed[j] = *reinterpret_cast<uint32_t*>(&h);
        }
        uint4* dst = reinterpret_cast<uint4*>(g_a16 + (size_t)row * K_DIM + tid * 16);
        dst[0] = make_uint4(packed[0], packed[1], packed[2], packed[3]);
        dst[1] = make_uint4(packed[4], packed[5], packed[6], packed[7]);
        if (tid == 0) g_sx[row] = scale;
    } else {
        int o = blockIdx.x - M_TOK;
        int g = tid >> 4;
        float z = zeros[o * NGRP + g];
        float s = scales[o * NGRP + g];

        const int4* Wrow = reinterpret_cast<const int4*>(W + (size_t)o * K_DIM) + tid * 4;
        uint32_t packed[8];
#pragma unroll
        for (int c = 0; c < 4; c++) {
            int4 w4 = Wrow[c];
            __half2 h0 = __floats2half2_rn(((float)w4.x - z) * s, ((float)w4.y - z) * s);
            __half2 h1 = __floats2half2_rn(((float)w4.z - z) * s, ((float)w4.w - z) * s);
            packed[2 * c]     = *reinterpret_cast<uint32_t*>(&h0);
            packed[2 * c + 1] = *reinterpret_cast<uint32_t*>(&h1);
        }
        uint4* dst = reinterpret_cast<uint4*>(g_b16 + (size_t)o * K_DIM + tid * 16);
        dst[0] = make_uint4(packed[0], packed[1], packed[2], packed[3]);
        dst[1] = make_uint4(packed[4], packed[5], packed[6], packed[7]);
    }
}

// ============================================================================
// GEMM: 128x256 block, 64x64 warp tiles, 4-stage cp.async,
//       boundary work rotated into the ks3 MMA shadow
// ============================================================================
#define BM 128
#define BN 256
#define NSTAGE 4
#define A_TILE (BM * 128)                 // 16384 bytes
#define B_TILE (BN * 128)                 // 32768 bytes
#define STAGE_B (A_TILE + B_TILE)         // 49152
#define SMEM_DYN (NSTAGE * STAGE_B + 1024)
#define KITERS (K_DIM / 64)               // 64

__device__ __forceinline__ uint32_t s2u(const void* p) {
    uint32_t a;
    asm("{ .reg .u64 t; cvta.to.shared.u64 t, %1; cvt.u32.u64 %0, t; }" : "=r"(a) : "l"(p));
    return a;
}
__device__ __forceinline__ uint32_t swz(uint32_t r, uint32_t c16) {
    uint32_t off = r * 128 + c16 * 16;
    return off ^ ((off >> 3) & 0x70);
}
__device__ __forceinline__ void ldsm4(uint32_t& d0, uint32_t& d1, uint32_t& d2, uint32_t& d3,
                                      uint32_t addr) {
    asm volatile("ldmatrix.sync.aligned.m8n8.x4.shared.b16 {%0,%1,%2,%3}, [%4];"
                 : "=r"(d0), "=r"(d1), "=r"(d2), "=r"(d3) : "r"(addr));
}
__device__ __forceinline__ void mma_f16(float& c0, float& c1, float& c2, float& c3,
                                        uint32_t a0, uint32_t a1, uint32_t a2, uint32_t a3,
                                        uint32_t b0, uint32_t b1) {
    asm volatile(
        "mma.sync.aligned.m16n8k16.row.col.f32.f16.f16.f32 "
        "{%0,%1,%2,%3}, {%4,%5,%6,%7}, {%8,%9}, {%0,%1,%2,%3};\n"
        : "+f"(c0), "+f"(c1), "+f"(c2), "+f"(c3)
        : "r"(a0), "r"(a1), "r"(a2), "r"(a3), "r"(b0), "r"(b1));
}

__global__ __launch_bounds__(256, 1) void gemm_kernel(float* __restrict__ out) {
    extern __shared__ char smem_raw[];
    char* sm = (char*)(((uintptr_t)smem_raw + 1023) & ~(uintptr_t)1023);
    uint32_t sbase = s2u(sm);

    int tid = threadIdx.x, lane = tid & 31, wid = tid >> 5;
    int warpm = wid & 1, warpn = wid >> 1;        // 2 x 4 warp grid, warp tile 64x64
    int gid = lane >> 2, tig = lane & 3;
    int bn = blockIdx.x, bm = blockIdx.y;

    uint32_t aoff[4][4], boff[4][4];
    {
        int g8 = lane >> 3, rin = lane & 7;
#pragma unroll
        for (int mt = 0; mt < 4; mt++)
#pragma unroll
            for (int ks = 0; ks < 4; ks++)
                aoff[mt][ks] = swz(warpm * 64 + mt * 16 + (g8 & 1) * 8 + rin, ks * 2 + (g8 >> 1));
#pragma unroll
        for (int p = 0; p < 4; p++)
#pragma unroll
            for (int ks = 0; ks < 4; ks++)
                boff[p][ks] = A_TILE + swz(warpn * 64 + p * 16 + (g8 >> 1) * 8 + rin, ks * 2 + (g8 & 1));
    }

    const char* Ag = (const char*)g_a16 + (size_t)bm * BM * KB2;
    const char* Bg = (const char*)g_b16 + (size_t)bn * BN * KB2;

    uint32_t sa_off[4], sb_off[8], ga_off[4], gb_off[8];
#pragma unroll
    for (int i = 0; i < 4; i++) {
        int seg = tid + i * 256;
        int r = seg >> 3, c16 = seg & 7;
        sa_off[i] = swz(r, c16);
        ga_off[i] = (uint32_t)(r * KB2 + c16 * 16);
    }
#pragma unroll
    for (int i = 0; i < 8; i++) {
        int seg = tid + i * 256;
        int r = seg >> 3, c16 = seg & 7;
        sb_off[i] = A_TILE + swz(r, c16);
        gb_off[i] = (uint32_t)(r * KB2 + c16 * 16);
    }

#define ISSUE(kc)                                                                            \
    {                                                                                        \
        uint32_t st = sbase + ((kc) & 3) * STAGE_B;                                          \
        uint32_t kb = (kc) * 128;                                                            \
        _Pragma("unroll") for (int i = 0; i < 4; i++)                                        \
            asm volatile("cp.async.cg.shared.global [%0], [%1], 16;"                         \
                         :: "r"(st + sa_off[i]), "l"(Ag + ga_off[i] + kb) : "memory");       \
        _Pragma("unroll") for (int i = 0; i < 8; i++)                                        \
            asm volatile("cp.async.cg.shared.global [%0], [%1], 16;"                         \
                         :: "r"(st + sb_off[i]), "l"(Bg + gb_off[i] + kb) : "memory");       \
        asm volatile("cp.async.commit_group;" ::: "memory");                                 \
    }

#define LOADFRAG(buf, sA, ks)                                                    \
    {                                                                            \
        _Pragma("unroll") for (int mt = 0; mt < 4; mt++)                         \
            ldsm4(a[buf][mt][0], a[buf][mt][1], a[buf][mt][2], a[buf][mt][3],    \
                  (sA) + aoff[mt][ks]);                                          \
        _Pragma("unroll") for (int p = 0; p < 4; p++)                            \
            ldsm4(b[buf][p][0], b[buf][p][1], b[buf][p][2], b[buf][p][3],        \
                  (sA) + boff[p][ks]);                                           \
    }

#define MMA_ALL(buf)                                                                         \
    {                                                                                        \
        _Pragma("unroll") for (int mt = 0; mt < 4; mt++)                                     \
            _Pragma("unroll") for (int nt = 0; nt < 8; nt++)                                 \
                mma_f16(c[mt][nt][0], c[mt][nt][1], c[mt][nt][2], c[mt][nt][3],              \
                        a[buf][mt][0], a[buf][mt][1], a[buf][mt][2], a[buf][mt][3],          \
                        b[buf][nt >> 1][(nt & 1) * 2], b[buf][nt >> 1][(nt & 1) * 2 + 1]);   \
    }

    float c[4][8][4];
#pragma unroll
    for (int mt = 0; mt < 4; mt++)
#pragma unroll
        for (int nt = 0; nt < 8; nt++)
#pragma unroll
            for (int r = 0; r < 4; r++) c[mt][nt][r] = 0.0f;

    uint32_t a[2][4][4], b[2][4][4];

    // prologue: fill 3 stages; wait for stage 0; load its ks0 fragments
    ISSUE(0); ISSUE(1); ISSUE(2);
    asm volatile("cp.async.wait_group 2;" ::: "memory");
    __syncthreads();
    LOADFRAG(0, sbase, 0);

    for (int kc = 0; kc < KITERS; ++kc) {
        uint32_t sA = sbase + (kc & 3) * STAGE_B;
        // ks0..ks2: prefetch next fragments, alternate buffers (0,1,0,1)
        LOADFRAG(1, sA, 1);
        MMA_ALL(0);
        LOADFRAG(0, sA, 2);
        MMA_ALL(1);
        LOADFRAG(1, sA, 3);
        MMA_ALL(0);
        if (kc + 1 < KITERS) {
            // boundary work hidden in the shadow of ks3's MMAs:
            asm volatile("cp.async.wait_group 1;" ::: "memory");   // stage kc+1 complete (mine)
            __syncthreads();                                        // everyone's kc+1 visible; slot reuse safe
            if (kc + 3 < KITERS) ISSUE(kc + 3);
            LOADFRAG(0, sbase + ((kc + 1) & 3) * STAGE_B, 0);       // next kc ks0
            MMA_ALL(1);                                             // ks3
        } else {
            MMA_ALL(1);
        }
    }

    // epilogue: out[m,o] = sx[m] * acc  (B already carries weight scales)
#pragma unroll
    for (int mt = 0; mt < 4; ++mt) {
        int rlo = bm * BM + warpm * 64 + mt * 16 + gid;
        int rhi = rlo + 8;
        float sxl = g_sx[rlo];
        float sxh = g_sx[rhi];
#pragma unroll
        for (int nt = 0; nt < 8; ++nt) {
            int o0 = bn * BN + warpn * 64 + nt * 8 + tig * 2;
            float2 vlo = make_float2(sxl * c[mt][nt][0], sxl * c[mt][nt][1]);
            float2 vhi = make_float2(sxh * c[mt][nt][2], sxh * c[mt][nt][3]);
            *reinterpret_cast<float2*>(out + (size_t)rlo * N_OUT + o0) = vlo;
            *reinterpret_cast<float2*>(out + (size_t)rhi * N_OUT + o0) = vhi;
        }
    }
}

// ============================================================================
// launch
// ============================================================================
extern "C" void kernel_launch(void* const* d_in, const int* in_sizes, int n_in,
                              void* d_out, int out_size) {
    const float* x      = (const float*)d_in[0];
    const int*   w      = (const int*)d_in[1];     // int8 upcast to int32 by harness
    const float* scales = (const float*)d_in[2];
    const float* zeros  = (const float*)d_in[3];
    float* out = (float*)d_out;

    cudaFuncSetAttribute(gemm_kernel, cudaFuncAttributeMaxDynamicSharedMemorySize, SMEM_DYN);

    prep_kernel<<<M_TOK + N_OUT, 256>>>(x, w, scales, zeros);
    gemm_kernel<<<dim3(N_OUT / BN, M_TOK / BM), 256, SMEM_DYN>>>(out);
}

// round 9
// speedup vs baseline: 3.3218x; 1.0002x over previous
#include <cuda_runtime.h>
#include <cuda_fp16.h>
#include <cstdint>

#define M_TOK 8192
#define K_DIM 4096
#define N_OUT 4096
#define NGRP  16
#define KB2   (K_DIM * 2)               // row stride in bytes (fp16)

// ---- scratch (device globals; no allocation allowed) ----
__device__ __align__(16) __half g_a16[(size_t)M_TOK * K_DIM];   // fp16(q - zp), exact ints
__device__ __align__(16) __half g_b16[(size_t)N_OUT * K_DIM];   // fp16((w - z) * s)
__device__ float g_sx[M_TOK];                                    // per-token scale

// ============================================================================
// Fused prep kernel: blocks [0,8192) per-token quant -> g_a16,
//                    blocks [8192,12288) weight dequant -> g_b16
// ============================================================================
__global__ __launch_bounds__(256) void prep_kernel(const float* __restrict__ x,
                                                   const int* __restrict__ W,
                                                   const float* __restrict__ scales,
                                                   const float* __restrict__ zeros) {
    int tid = threadIdx.x;
    if (blockIdx.x < M_TOK) {
        int row = blockIdx.x;
        const float4* xr4 = reinterpret_cast<const float4*>(x + (size_t)row * K_DIM) + tid * 4;

        float4 v[4];
#pragma unroll
        for (int i = 0; i < 4; i++) v[i] = xr4[i];

        float mn = 0.0f, mx = 0.0f;
#pragma unroll
        for (int i = 0; i < 4; i++) {
            mn = fminf(mn, fminf(fminf(v[i].x, v[i].y), fminf(v[i].z, v[i].w)));
            mx = fmaxf(mx, fmaxf(fmaxf(v[i].x, v[i].y), fmaxf(v[i].z, v[i].w)));
        }
#pragma unroll
        for (int off = 16; off; off >>= 1) {
            mn = fminf(mn, __shfl_xor_sync(0xffffffffu, mn, off));
            mx = fmaxf(mx, __shfl_xor_sync(0xffffffffu, mx, off));
        }
        __shared__ float smn[8], smx[8];
        if ((tid & 31) == 0) { smn[tid >> 5] = mn; smx[tid >> 5] = mx; }
        __syncthreads();
        mn = smn[0]; mx = smx[0];
#pragma unroll
        for (int i = 1; i < 8; i++) { mn = fminf(mn, smn[i]); mx = fmaxf(mx, smx[i]); }

        float scale = fmaxf((mx - mn) / 255.0f, 1.1920928955078125e-07f);
        float a = mn / scale, b = mx / scale;
        float t = (-128.0f + a) + (127.0f + b);
        float zp0 = (t > 0.0f) ? (-128.0f - a) : (127.0f - b);
        float zpf = fminf(fmaxf(rintf(zp0), -128.0f), 127.0f);

        const float* pv = reinterpret_cast<const float*>(v);
        uint32_t packed[8];
#pragma unroll
        for (int j = 0; j < 8; j++) {
            float q0 = fminf(fmaxf(rintf(pv[2 * j] / scale) + zpf, -128.0f), 127.0f);
            float q1 = fminf(fmaxf(rintf(pv[2 * j + 1] / scale) + zpf, -128.0f), 127.0f);
            __half2 h = __floats2half2_rn(q0 - zpf, q1 - zpf);   // exact ints in [-255,255]
            packed[j] = *reinterpret_cast<uint32_t*>(&h);
        }
        uint4* dst = reinterpret_cast<uint4*>(g_a16 + (size_t)row * K_DIM + tid * 16);
        dst[0] = make_uint4(packed[0], packed[1], packed[2], packed[3]);
        dst[1] = make_uint4(packed[4], packed[5], packed[6], packed[7]);
        if (tid == 0) g_sx[row] = scale;
    } else {
        int o = blockIdx.x - M_TOK;
        int g = tid >> 4;
        float z = zeros[o * NGRP + g];
        float s = scales[o * NGRP + g];

        const int4* Wrow = reinterpret_cast<const int4*>(W + (size_t)o * K_DIM) + tid * 4;
        uint32_t packed[8];
#pragma unroll
        for (int c = 0; c < 4; c++) {
            int4 w4 = Wrow[c];
            __half2 h0 = __floats2half2_rn(((float)w4.x - z) * s, ((float)w4.y - z) * s);
            __half2 h1 = __floats2half2_rn(((float)w4.z - z) * s, ((float)w4.w - z) * s);
            packed[2 * c]     = *reinterpret_cast<uint32_t*>(&h0);
            packed[2 * c + 1] = *reinterpret_cast<uint32_t*>(&h1);
        }
        uint4* dst = reinterpret_cast<uint4*>(g_b16 + (size_t)o * K_DIM + tid * 16);
        dst[0] = make_uint4(packed[0], packed[1], packed[2], packed[3]);
        dst[1] = make_uint4(packed[4], packed[5], packed[6], packed[7]);
    }
}

// ============================================================================
// GEMM: 128x256 block, 64x64 warp tiles, 4-stage cp.async,
//       boundary in MMA shadow, register-dieted offsets (no spills)
// ============================================================================
#define BM 128
#define BN 256
#define NSTAGE 4
#define A_TILE (BM * 128)                 // 16384 bytes
#define B_TILE (BN * 128)                 // 32768 bytes
#define STAGE_B (A_TILE + B_TILE)         // 49152
#define SMEM_DYN (NSTAGE * STAGE_B + 1024)
#define KITERS (K_DIM / 64)               // 64
#define ROWSTEP (32 * KB2)                // gmem offset delta per cp.async slice

__device__ __forceinline__ uint32_t s2u(const void* p) {
    uint32_t a;
    asm("{ .reg .u64 t; cvta.to.shared.u64 t, %1; cvt.u32.u64 %0, t; }" : "=r"(a) : "l"(p));
    return a;
}
__device__ __forceinline__ uint32_t swz(uint32_t r, uint32_t c16) {
    uint32_t off = r * 128 + c16 * 16;
    return off ^ ((off >> 3) & 0x70);
}
__device__ __forceinline__ void ldsm4(uint32_t& d0, uint32_t& d1, uint32_t& d2, uint32_t& d3,
                                      uint32_t addr) {
    asm volatile("ldmatrix.sync.aligned.m8n8.x4.shared.b16 {%0,%1,%2,%3}, [%4];"
                 : "=r"(d0), "=r"(d1), "=r"(d2), "=r"(d3) : "r"(addr));
}
__device__ __forceinline__ void mma_f16(float& c0, float& c1, float& c2, float& c3,
                                        uint32_t a0, uint32_t a1, uint32_t a2, uint32_t a3,
                                        uint32_t b0, uint32_t b1) {
    asm volatile(
        "mma.sync.aligned.m16n8k16.row.col.f32.f16.f16.f32 "
        "{%0,%1,%2,%3}, {%4,%5,%6,%7}, {%8,%9}, {%0,%1,%2,%3};\n"
        : "+f"(c0), "+f"(c1), "+f"(c2), "+f"(c3)
        : "r"(a0), "r"(a1), "r"(a2), "r"(a3), "r"(b0), "r"(b1));
}

__global__ __launch_bounds__(256, 1) void gemm_kernel(float* __restrict__ out) {
    extern __shared__ char smem_raw[];
    char* sm = (char*)(((uintptr_t)smem_raw + 1023) & ~(uintptr_t)1023);
    uint32_t sbase = s2u(sm);

    int tid = threadIdx.x, lane = tid & 31, wid = tid >> 5;
    int warpm = wid & 1, warpn = wid >> 1;        // 2 x 4 warp grid, warp tile 64x64
    int gid = lane >> 2, tig = lane & 3;
    int bn = blockIdx.x, bm = blockIdx.y;

    // base ldmatrix offsets (ks=0); ks variant = base ^ (ks<<5)
    uint32_t aoffb[4], boffb[4];
    {
        int g8 = lane >> 3, rin = lane & 7;
#pragma unroll
        for (int mt = 0; mt < 4; mt++)
            aoffb[mt] = swz(warpm * 64 + mt * 16 + (g8 & 1) * 8 + rin, g8 >> 1);
#pragma unroll
        for (int p = 0; p < 4; p++)
            boffb[p] = A_TILE + swz(warpn * 64 + p * 16 + (g8 >> 1) * 8 + rin, g8 & 1);
    }

    const char* Ag = (const char*)g_a16 + (size_t)bm * BM * KB2;
    const char* Bg = (const char*)g_b16 + (size_t)bn * BN * KB2;

    // cp.async bases; slice i adds i*4096 (smem) / i*ROWSTEP (gmem)
    uint32_t sa0 = swz(tid >> 3, tid & 7);
    uint32_t g0  = (uint32_t)((tid >> 3) * KB2 + (tid & 7) * 16);

#define ISSUE(kc)                                                                              \
    {                                                                                          \
        uint32_t st = sbase + ((kc) & 3) * STAGE_B + sa0;                                      \
        uint32_t kb = g0 + (kc) * 128;                                                         \
        _Pragma("unroll") for (int i = 0; i < 4; i++)                                          \
            asm volatile("cp.async.cg.shared.global [%0], [%1], 16;"                           \
                         :: "r"(st + i * 4096), "l"(Ag + kb + i * ROWSTEP) : "memory");        \
        _Pragma("unroll") for (int i = 0; i < 8; i++)                                          \
            asm volatile("cp.async.cg.shared.global [%0], [%1], 16;"                           \
                         :: "r"(st + A_TILE + i * 4096), "l"(Bg + kb + i * ROWSTEP) : "memory"); \
        asm volatile("cp.async.commit_group;" ::: "memory");                                   \
    }

#define LOADFRAG(buf, sA, ks)                                                        \
    {                                                                                \
        _Pragma("unroll") for (int mt = 0; mt < 4; mt++)                             \
            ldsm4(a[buf][mt][0], a[buf][mt][1], a[buf][mt][2], a[buf][mt][3],        \
                  (sA) + (aoffb[mt] ^ ((ks) << 5)));                                 \
        _Pragma("unroll") for (int p = 0; p < 4; p++)                                \
            ldsm4(b[buf][p][0], b[buf][p][1], b[buf][p][2], b[buf][p][3],            \
                  (sA) + (boffb[p] ^ ((ks) << 5)));                                  \
    }

#define MMA_ALL(buf)                                                                         \
    {                                                                                        \
        _Pragma("unroll") for (int mt = 0; mt < 4; mt++)                                     \
            _Pragma("unroll") for (int nt = 0; nt < 8; nt++)                                 \
                mma_f16(c[mt][nt][0], c[mt][nt][1], c[mt][nt][2], c[mt][nt][3],              \
                        a[buf][mt][0], a[buf][mt][1], a[buf][mt][2], a[buf][mt][3],          \
                        b[buf][nt >> 1][(nt & 1) * 2], b[buf][nt >> 1][(nt & 1) * 2 + 1]);   \
    }

    float c[4][8][4];
#pragma unroll
    for (int mt = 0; mt < 4; mt++)
#pragma unroll
        for (int nt = 0; nt < 8; nt++)
#pragma unroll
            for (int r = 0; r < 4; r++) c[mt][nt][r] = 0.0f;

    uint32_t a[2][4][4], b[2][4][4];

    // prologue: fill 3 stages; wait for stage 0; load its ks0 fragments
    ISSUE(0); ISSUE(1); ISSUE(2);
    asm volatile("cp.async.wait_group 2;" ::: "memory");
    __syncthreads();
    LOADFRAG(0, sbase, 0);

    for (int kc = 0; kc < KITERS; ++kc) {
        uint32_t sA = sbase + (kc & 3) * STAGE_B;
        LOADFRAG(1, sA, 1);
        MMA_ALL(0);
        LOADFRAG(0, sA, 2);
        MMA_ALL(1);
        LOADFRAG(1, sA, 3);
        MMA_ALL(0);
        if (kc + 1 < KITERS) {
            // boundary hidden in the shadow of ks3's MMAs
            asm volatile("cp.async.wait_group 1;" ::: "memory");
            __syncthreads();
            if (kc + 3 < KITERS) ISSUE(kc + 3);
            LOADFRAG(0, sbase + ((kc + 1) & 3) * STAGE_B, 0);
            MMA_ALL(1);
        } else {
            MMA_ALL(1);
        }
    }

    // epilogue: out[m,o] = sx[m] * acc  (B already carries weight scales)
#pragma unroll
    for (int mt = 0; mt < 4; ++mt) {
        int rlo = bm * BM + warpm * 64 + mt * 16 + gid;
        int rhi = rlo + 8;
        float sxl = g_sx[rlo];
        float sxh = g_sx[rhi];
#pragma unroll
        for (int nt = 0; nt < 8; ++nt) {
            int o0 = bn * BN + warpn * 64 + nt * 8 + tig * 2;
            float2 vlo = make_float2(sxl * c[mt][nt][0], sxl * c[mt][nt][1]);
            float2 vhi = make_float2(sxh * c[mt][nt][2], sxh * c[mt][nt][3]);
            *reinterpret_cast<float2*>(out + (size_t)rlo * N_OUT + o0) = vlo;
            *reinterpret_cast<float2*>(out + (size_t)rhi * N_OUT + o0) = vhi;
        }
    }
}

// ============================================================================
// launch
// ============================================================================
extern "C" void kernel_launch(void* const* d_in, const int* in_sizes, int n_in,
                              void* d_out, int out_size) {
    const float* x      = (const float*)d_in[0];
    const int*   w      = (const int*)d_in[1];     // int8 upcast to int32 by harness
    const float* scales = (const float*)d_in[2];
    const float* zeros  = (const float*)d_in[3];
    float* out = (float*)d_out;

    cudaFuncSetAttribute(gemm_kernel, cudaFuncAttributeMaxDynamicSharedMemorySize, SMEM_DYN);

    prep_kernel<<<M_TOK + N_OUT, 256>>>(x, w, scales, zeros);
    gemm_kernel<<<dim3(N_OUT / BN, M_TOK / BM), 256, SMEM_DYN>>>(out);
}